// round 1
// baseline (speedup 1.0000x reference)
#include <cuda_runtime.h>

// Coefficients computed once per launch by a 1-thread prelude kernel:
// g_coef[0] = a * alpha, g_coef[1] = a * beta, g_coef[2] = b
__device__ float g_coef[3];

struct C2 { float r, i; };
__device__ __forceinline__ C2 cmul(C2 a, C2 b) {
    return { a.r * b.r - a.i * b.i, a.r * b.i + a.i * b.r };
}
__device__ __forceinline__ C2 cadd(C2 a, C2 b) { return { a.r + b.r, a.i + b.i }; }

__device__ __forceinline__ void mm2(const C2 A[2][2], const C2 B[2][2], C2 O[2][2]) {
    for (int r = 0; r < 2; r++)
        for (int c = 0; c < 2; c++)
            O[r][c] = cadd(cmul(A[r][0], B[0][c]), cmul(A[r][1], B[1][c]));
}

// U_layer = RZ(w2) @ RY(w1) @ RX(w0)
__device__ __forceinline__ void layer_unitary(const float* w, C2 U[2][2]) {
    float h0 = 0.5f * w[0], h1 = 0.5f * w[1], h2 = 0.5f * w[2];
    float c0, s0, c1, s1, c2, s2;
    sincosf(h0, &s0, &c0);
    sincosf(h1, &s1, &c1);
    sincosf(h2, &s2, &c2);
    C2 rx[2][2] = { { {c0, 0.f}, {0.f, -s0} }, { {0.f, -s0}, {c0, 0.f} } };
    C2 ry[2][2] = { { {c1, 0.f}, {-s1, 0.f} }, { {s1, 0.f}, {c1, 0.f} } };
    C2 rz[2][2] = { { {c2, -s2}, {0.f, 0.f} }, { {0.f, 0.f}, {c2, s2} } };
    C2 t[2][2];
    mm2(ry, rx, t);
    mm2(rz, t, U);
}

__global__ void qpinn_precompute(const float* __restrict__ weights,
                                 const float* __restrict__ a,
                                 const float* __restrict__ b) {
    // Single thread: build total unitary U = U(layer1) @ U(layer0)
    C2 U0[2][2], U1[2][2], U[2][2];
    layer_unitary(weights + 0, U0);
    layer_unitary(weights + 3, U1);
    mm2(U1, U0, U);

    // M = U^dagger Z U (Hermitian, traceless). z = M00*cos(x) + Re(M01)*sin(x)
    float alpha = (U[0][0].r * U[0][0].r + U[0][0].i * U[0][0].i)
                - (U[1][0].r * U[1][0].r + U[1][0].i * U[1][0].i);
    float beta  = (U[0][0].r * U[0][1].r + U[0][0].i * U[0][1].i)
                - (U[1][0].r * U[1][1].r + U[1][0].i * U[1][1].i);

    float av = a[0], bv = b[0];
    g_coef[0] = av * alpha;
    g_coef[1] = av * beta;
    g_coef[2] = bv;
}

__global__ void __launch_bounds__(256)
qpinn_stream(const float4* __restrict__ x4, float4* __restrict__ out4, int n4) {
    const float ca = g_coef[0];
    const float cb = g_coef[1];
    const float bb = g_coef[2];

    int idx = blockIdx.x * blockDim.x + threadIdx.x;
    if (idx >= n4) return;

    float4 v = x4[idx];
    float4 o;
    float s, c;
    sincosf(v.x, &s, &c); o.x = fmaf(ca, c, fmaf(cb, s, bb));
    sincosf(v.y, &s, &c); o.y = fmaf(ca, c, fmaf(cb, s, bb));
    sincosf(v.z, &s, &c); o.z = fmaf(ca, c, fmaf(cb, s, bb));
    sincosf(v.w, &s, &c); o.w = fmaf(ca, c, fmaf(cb, s, bb));
    out4[idx] = o;
}

__global__ void qpinn_stream_tail(const float* __restrict__ x, float* __restrict__ out,
                                  int start, int n) {
    const float ca = g_coef[0];
    const float cb = g_coef[1];
    const float bb = g_coef[2];
    int idx = start + blockIdx.x * blockDim.x + threadIdx.x;
    if (idx >= n) return;
    float s, c;
    sincosf(x[idx], &s, &c);
    out[idx] = fmaf(ca, c, fmaf(cb, s, bb));
}

extern "C" void kernel_launch(void* const* d_in, const int* in_sizes, int n_in,
                              void* d_out, int out_size) {
    const float* x       = (const float*)d_in[0];
    const float* weights = (const float*)d_in[1];
    const float* a       = (const float*)d_in[2];
    const float* b       = (const float*)d_in[3];
    float* out = (float*)d_out;

    int n = in_sizes[0];

    qpinn_precompute<<<1, 1>>>(weights, a, b);

    int n4 = n / 4;
    if (n4 > 0) {
        int threads = 256;
        int blocks = (n4 + threads - 1) / threads;
        qpinn_stream<<<blocks, threads>>>((const float4*)x, (float4*)out, n4);
    }
    int rem = n - n4 * 4;
    if (rem > 0) {
        qpinn_stream_tail<<<1, 256>>>(x, out, n4 * 4, n);
    }
}

// round 2
// speedup vs baseline: 1.2412x; 1.2412x over previous
#include <cuda_runtime.h>

struct C2 { float r, i; };
__device__ __forceinline__ C2 cmul(C2 a, C2 b) {
    return { a.r * b.r - a.i * b.i, a.r * b.i + a.i * b.r };
}
__device__ __forceinline__ C2 cadd(C2 a, C2 b) { return { a.r + b.r, a.i + b.i }; }

__device__ __forceinline__ void mm2(const C2 A[2][2], const C2 B[2][2], C2 O[2][2]) {
#pragma unroll
    for (int r = 0; r < 2; r++)
#pragma unroll
        for (int c = 0; c < 2; c++)
            O[r][c] = cadd(cmul(A[r][0], B[0][c]), cmul(A[r][1], B[1][c]));
}

// U_layer = RZ(w2) @ RY(w1) @ RX(w0)
__device__ __forceinline__ void layer_unitary(float w0, float w1, float w2, C2 U[2][2]) {
    float c0, s0, c1, s1, c2, s2;
    __sincosf(0.5f * w0, &s0, &c0);
    __sincosf(0.5f * w1, &s1, &c1);
    __sincosf(0.5f * w2, &s2, &c2);
    C2 rx[2][2] = { { {c0, 0.f}, {0.f, -s0} }, { {0.f, -s0}, {c0, 0.f} } };
    C2 ry[2][2] = { { {c1, 0.f}, {-s1, 0.f} }, { {s1, 0.f}, {c1, 0.f} } };
    C2 rz[2][2] = { { {c2, -s2}, {0.f, 0.f} }, { {0.f, 0.f}, {c2, s2} } };
    C2 t[2][2];
    mm2(ry, rx, t);
    mm2(rz, t, U);
}

// Collapse the whole circuit: out = a*(alpha*cos(x) + beta*sin(x)) + b
__device__ __forceinline__ void compute_coefs(const float* __restrict__ weights,
                                              const float* __restrict__ a,
                                              const float* __restrict__ b,
                                              float& ca, float& cb, float& bb) {
    C2 U0[2][2], U1[2][2], U[2][2];
    layer_unitary(__ldg(weights + 0), __ldg(weights + 1), __ldg(weights + 2), U0);
    layer_unitary(__ldg(weights + 3), __ldg(weights + 4), __ldg(weights + 5), U1);
    mm2(U1, U0, U);

    // M = U^dagger Z U; z = alpha*cos(x) + beta*sin(x)
    float alpha = (U[0][0].r * U[0][0].r + U[0][0].i * U[0][0].i)
                - (U[1][0].r * U[1][0].r + U[1][0].i * U[1][0].i);
    float beta  = (U[0][0].r * U[0][1].r + U[0][0].i * U[0][1].i)
                - (U[1][0].r * U[1][1].r + U[1][0].i * U[1][1].i);

    float av = __ldg(a), bv = __ldg(b);
    ca = av * alpha;
    cb = av * beta;
    bb = bv;
}

__global__ void __launch_bounds__(256)
qpinn_fused(const float4* __restrict__ x4, float4* __restrict__ out4, int n4,
            const float* __restrict__ x, float* __restrict__ out, int n,
            const float* __restrict__ weights,
            const float* __restrict__ a, const float* __restrict__ b) {
    float ca, cb, bb;
    compute_coefs(weights, a, b, ca, cb, bb);

    const int stride = gridDim.x * blockDim.x;
    int idx = blockIdx.x * blockDim.x + threadIdx.x;

    for (; idx < n4; idx += stride) {
        float4 v = __ldcs(x4 + idx);
        float4 o;
        float s, c;
        __sincosf(v.x, &s, &c); o.x = fmaf(ca, c, fmaf(cb, s, bb));
        __sincosf(v.y, &s, &c); o.y = fmaf(ca, c, fmaf(cb, s, bb));
        __sincosf(v.z, &s, &c); o.z = fmaf(ca, c, fmaf(cb, s, bb));
        __sincosf(v.w, &s, &c); o.w = fmaf(ca, c, fmaf(cb, s, bb));
        __stcs(out4 + idx, o);
    }

    // Scalar tail (n not divisible by 4)
    int tail = n4 * 4 + (blockIdx.x * blockDim.x + threadIdx.x);
    if (tail < n) {
        float s, c;
        __sincosf(__ldcs(x + tail), &s, &c);
        __stcs(out + tail, fmaf(ca, c, fmaf(cb, s, bb)));
    }
}

extern "C" void kernel_launch(void* const* d_in, const int* in_sizes, int n_in,
                              void* d_out, int out_size) {
    const float* x       = (const float*)d_in[0];
    const float* weights = (const float*)d_in[1];
    const float* a       = (const float*)d_in[2];
    const float* b       = (const float*)d_in[3];
    float* out = (float*)d_out;

    int n = in_sizes[0];
    int n4 = n / 4;

    const int threads = 256;
    int blocks = 148 * 16;  // grid-stride; ~7 float4 per thread at N=16.7M
    int max_blocks = (n4 + threads - 1) / threads;
    if (max_blocks == 0) max_blocks = 1;
    if (blocks > max_blocks) blocks = max_blocks;

    qpinn_fused<<<blocks, threads>>>((const float4*)x, (float4*)out, n4,
                                     x, out, n, weights, a, b);
}

// round 3
// speedup vs baseline: 1.3653x; 1.1000x over previous
#include <cuda_runtime.h>

struct C2 { float r, i; };
__device__ __forceinline__ C2 cmul(C2 a, C2 b) {
    return { a.r * b.r - a.i * b.i, a.r * b.i + a.i * b.r };
}
__device__ __forceinline__ C2 cadd(C2 a, C2 b) { return { a.r + b.r, a.i + b.i }; }

__device__ __forceinline__ void mm2(const C2 A[2][2], const C2 B[2][2], C2 O[2][2]) {
#pragma unroll
    for (int r = 0; r < 2; r++)
#pragma unroll
        for (int c = 0; c < 2; c++)
            O[r][c] = cadd(cmul(A[r][0], B[0][c]), cmul(A[r][1], B[1][c]));
}

// U_layer = RZ(w2) @ RY(w1) @ RX(w0)
__device__ __forceinline__ void layer_unitary(float w0, float w1, float w2, C2 U[2][2]) {
    float c0, s0, c1, s1, c2, s2;
    __sincosf(0.5f * w0, &s0, &c0);
    __sincosf(0.5f * w1, &s1, &c1);
    __sincosf(0.5f * w2, &s2, &c2);
    C2 rx[2][2] = { { {c0, 0.f}, {0.f, -s0} }, { {0.f, -s0}, {c0, 0.f} } };
    C2 ry[2][2] = { { {c1, 0.f}, {-s1, 0.f} }, { {s1, 0.f}, {c1, 0.f} } };
    C2 rz[2][2] = { { {c2, -s2}, {0.f, 0.f} }, { {0.f, 0.f}, {c2, s2} } };
    C2 t[2][2];
    mm2(ry, rx, t);
    mm2(rz, t, U);
}

// Collapse the whole circuit: out = a*(alpha*cos(x) + beta*sin(x)) + b
__device__ __forceinline__ void compute_coefs(const float* __restrict__ weights,
                                              const float* __restrict__ a,
                                              const float* __restrict__ b,
                                              float& ca, float& cb, float& bb) {
    C2 U0[2][2], U1[2][2], U[2][2];
    layer_unitary(__ldg(weights + 0), __ldg(weights + 1), __ldg(weights + 2), U0);
    layer_unitary(__ldg(weights + 3), __ldg(weights + 4), __ldg(weights + 5), U1);
    mm2(U1, U0, U);

    float alpha = (U[0][0].r * U[0][0].r + U[0][0].i * U[0][0].i)
                - (U[1][0].r * U[1][0].r + U[1][0].i * U[1][0].i);
    float beta  = (U[0][0].r * U[0][1].r + U[0][0].i * U[0][1].i)
                - (U[1][0].r * U[1][1].r + U[1][0].i * U[1][1].i);

    float av = __ldg(a), bv = __ldg(b);
    ca = av * alpha;
    cb = av * beta;
    bb = bv;
}

__device__ __forceinline__ float4 eval4(float4 v, float ca, float cb, float bb) {
    float4 o; float s, c;
    __sincosf(v.x, &s, &c); o.x = fmaf(ca, c, fmaf(cb, s, bb));
    __sincosf(v.y, &s, &c); o.y = fmaf(ca, c, fmaf(cb, s, bb));
    __sincosf(v.z, &s, &c); o.z = fmaf(ca, c, fmaf(cb, s, bb));
    __sincosf(v.w, &s, &c); o.w = fmaf(ca, c, fmaf(cb, s, bb));
    return o;
}

__global__ void __launch_bounds__(256)
qpinn_fused(const float4* __restrict__ x4, float4* __restrict__ out4, int n4,
            const float* __restrict__ x, float* __restrict__ out, int n,
            const float* __restrict__ weights,
            const float* __restrict__ a, const float* __restrict__ b) {
    float ca, cb, bb;
    compute_coefs(weights, a, b, ca, cb, bb);

    const int stride = gridDim.x * blockDim.x;
    int idx = blockIdx.x * blockDim.x + threadIdx.x;

    // Main loop: 4 independent float4 loads in flight per iteration (MLP=4)
    for (; idx + 3 * stride < n4; idx += 4 * stride) {
        float4 v0 = __ldcs(x4 + idx);
        float4 v1 = __ldcs(x4 + idx + stride);
        float4 v2 = __ldcs(x4 + idx + 2 * stride);
        float4 v3 = __ldcs(x4 + idx + 3 * stride);
        __stcs(out4 + idx,              eval4(v0, ca, cb, bb));
        __stcs(out4 + idx + stride,     eval4(v1, ca, cb, bb));
        __stcs(out4 + idx + 2 * stride, eval4(v2, ca, cb, bb));
        __stcs(out4 + idx + 3 * stride, eval4(v3, ca, cb, bb));
    }
    // Remainder float4s
    for (; idx < n4; idx += stride) {
        __stcs(out4 + idx, eval4(__ldcs(x4 + idx), ca, cb, bb));
    }
    // Scalar tail (n not divisible by 4)
    int tail = n4 * 4 + (blockIdx.x * blockDim.x + threadIdx.x);
    if (tail < n) {
        float s, c;
        __sincosf(__ldcs(x + tail), &s, &c);
        __stcs(out + tail, fmaf(ca, c, fmaf(cb, s, bb)));
    }
}

extern "C" void kernel_launch(void* const* d_in, const int* in_sizes, int n_in,
                              void* d_out, int out_size) {
    const float* x       = (const float*)d_in[0];
    const float* weights = (const float*)d_in[1];
    const float* a       = (const float*)d_in[2];
    const float* b       = (const float*)d_in[3];
    float* out = (float*)d_out;

    int n = in_sizes[0];
    int n4 = n / 4;

    const int threads = 256;
    // Each thread handles 4 float4s in one batched iteration:
    // 4096 blocks * 256 threads * 4 * 4 floats = 16,777,216 = N exactly.
    long long want = ((long long)n4 + threads * 4 - 1) / (threads * 4);
    int blocks = (int)want;
    if (blocks < 1) blocks = 1;
    if (blocks > 65535 * 32) blocks = 65535 * 32;

    qpinn_fused<<<blocks, threads>>>((const float4*)x, (float4*)out, n4,
                                     x, out, n, weights, a, b);
}